// round 1
// baseline (speedup 1.0000x reference)
#include <cuda_runtime.h>
#include <math.h>

#define NMAT 4096
#define INF  1024
#define OUTF 1024
#define NB   8
#define KDIM (INF * 9)   // 9216

// Scratch (allocation-free rule: __device__ globals)
__device__ float g_A[(size_t)NMAT * KDIM];   // [4096, 9216]  ~151 MB
__device__ float g_W[(size_t)OUTF * KDIM];   // [1024, 9216]  ~37.7 MB

// ---------------------------------------------------------------------------
// Stage 1: A[n, i*9+0] = silu(x[n,i]); A[n, i*9+1+b] = cubic B-spline basis_b
// Knots: t_j = (j-3)*h + lo, j=0..11, h=0.4, lo=-1  =>  t in [-2.2, 2.2]
// ---------------------------------------------------------------------------
__global__ void build_A_kernel(const float* __restrict__ x) {
    int idx = blockIdx.x * blockDim.x + threadIdx.x;
    if (idx >= NMAT * INF) return;
    float v = x[idx];

    // SiLU
    float s = v / (1.0f + expf(-v));

    const float h  = 0.4f;
    const float lo = -1.0f;

    // degree-0 indicators over the 11 intervals
    float b[11];
#pragma unroll
    for (int j = 0; j < 11; j++) {
        float t0 = (float)(j - 3) * h + lo;
        float t1 = (float)(j - 2) * h + lo;
        b[j] = (v >= t0 && v < t1) ? 1.0f : 0.0f;
    }
    // Cox-de Boor: uniform knots -> all denominators are k*h (+eps)
#pragma unroll
    for (int k = 1; k <= 3; k++) {
        float inv = 1.0f / ((float)k * h + 1e-8f);
#pragma unroll
        for (int j = 0; j + k < 11; j++) {
            float tj   = (float)(j - 3) * h + lo;
            float tjk1 = (float)(j + k - 2) * h + lo;   // t_{j+k+1}
            b[j] = (v - tj) * inv * b[j] + (tjk1 - v) * inv * b[j + 1];
        }
    }

    float* dst = g_A + (size_t)idx * 9;
    dst[0] = s;
#pragma unroll
    for (int j = 0; j < NB; j++) dst[1 + j] = b[j];
}

// ---------------------------------------------------------------------------
// Stage 2: W[o, i*9+0] = base_weight[o,i]; W[o, i*9+1+b] = spline_weight[o,i,b]
// ---------------------------------------------------------------------------
__global__ void pack_W_kernel(const float* __restrict__ bw,
                              const float* __restrict__ sw) {
    int idx = blockIdx.x * blockDim.x + threadIdx.x;   // o*INF + i
    if (idx >= OUTF * INF) return;
    float* dst = g_W + (size_t)idx * 9;
    dst[0] = bw[idx];
    const float* s = sw + (size_t)idx * NB;
#pragma unroll
    for (int j = 0; j < NB; j++) dst[1 + j] = s[j];
}

// ---------------------------------------------------------------------------
// Stage 3: C[m, n] = sum_k A[m,k] * W[n,k] + bias[n]
// 128x128x16 tiles, 256 threads, 8x8 per thread, fp32.
// ---------------------------------------------------------------------------
#define BM 128
#define BN 128
#define BK 16
#define TM 8
#define TN 8
#define LDA (BM + 4)   // smem pad to break STS conflicts

__global__ void __launch_bounds__(256, 2)
gemm_kernel(const float* __restrict__ bias, float* __restrict__ C) {
    __shared__ float As[BK][LDA];
    __shared__ float Bs[BK][LDA];

    const int bm = blockIdx.y * BM;
    const int bn = blockIdx.x * BN;
    const int tid = threadIdx.x;
    const int tx = tid % 16;   // output-col group
    const int ty = tid / 16;   // output-row group

    const float* Aptr = g_A + (size_t)bm * KDIM;
    const float* Bptr = g_W + (size_t)bn * KDIM;

    // loader mapping: each thread loads 2x float4 from A and 2x from W
    const int lrow = tid >> 2;          // 0..63
    const int lcol = (tid & 3) * 4;     // 0,4,8,12

    float acc[TM][TN];
#pragma unroll
    for (int i = 0; i < TM; i++)
#pragma unroll
        for (int j = 0; j < TN; j++) acc[i][j] = 0.0f;

    for (int k0 = 0; k0 < KDIM; k0 += BK) {
#pragma unroll
        for (int r = 0; r < 2; r++) {
            int row = lrow + r * 64;
            float4 va = *(const float4*)(Aptr + (size_t)row * KDIM + k0 + lcol);
            As[lcol + 0][row] = va.x;
            As[lcol + 1][row] = va.y;
            As[lcol + 2][row] = va.z;
            As[lcol + 3][row] = va.w;
            float4 vb = *(const float4*)(Bptr + (size_t)row * KDIM + k0 + lcol);
            Bs[lcol + 0][row] = vb.x;
            Bs[lcol + 1][row] = vb.y;
            Bs[lcol + 2][row] = vb.z;
            Bs[lcol + 3][row] = vb.w;
        }
        __syncthreads();

#pragma unroll
        for (int kk = 0; kk < BK; kk++) {
            float a[TM], bvec[TN];
            float4 a0 = *(const float4*)&As[kk][ty * TM + 0];
            float4 a1 = *(const float4*)&As[kk][ty * TM + 4];
            a[0] = a0.x; a[1] = a0.y; a[2] = a0.z; a[3] = a0.w;
            a[4] = a1.x; a[5] = a1.y; a[6] = a1.z; a[7] = a1.w;
            float4 b0 = *(const float4*)&Bs[kk][tx * TN + 0];
            float4 b1 = *(const float4*)&Bs[kk][tx * TN + 4];
            bvec[0] = b0.x; bvec[1] = b0.y; bvec[2] = b0.z; bvec[3] = b0.w;
            bvec[4] = b1.x; bvec[5] = b1.y; bvec[6] = b1.z; bvec[7] = b1.w;
#pragma unroll
            for (int i = 0; i < TM; i++)
#pragma unroll
                for (int j = 0; j < TN; j++)
                    acc[i][j] = fmaf(a[i], bvec[j], acc[i][j]);
        }
        __syncthreads();
    }

    // epilogue: add bias, vectorized store
    const int col0 = bn + tx * TN;
    float bias0[TN];
#pragma unroll
    for (int j = 0; j < TN; j++) bias0[j] = bias[col0 + j];

#pragma unroll
    for (int i = 0; i < TM; i++) {
        int row = bm + ty * TM + i;
        float4 o0, o1;
        o0.x = acc[i][0] + bias0[0];
        o0.y = acc[i][1] + bias0[1];
        o0.z = acc[i][2] + bias0[2];
        o0.w = acc[i][3] + bias0[3];
        o1.x = acc[i][4] + bias0[4];
        o1.y = acc[i][5] + bias0[5];
        o1.z = acc[i][6] + bias0[6];
        o1.w = acc[i][7] + bias0[7];
        float* dst = C + (size_t)row * OUTF + col0;
        *(float4*)(dst + 0) = o0;
        *(float4*)(dst + 4) = o1;
    }
}

// ---------------------------------------------------------------------------
extern "C" void kernel_launch(void* const* d_in, const int* in_sizes, int n_in,
                              void* d_out, int out_size) {
    const float* x    = (const float*)d_in[0];  // [4096, 1024]
    const float* bw   = (const float*)d_in[1];  // [1024, 1024]
    const float* bias = (const float*)d_in[2];  // [1024]
    const float* sw   = (const float*)d_in[3];  // [1024, 1024, 8]
    float* out = (float*)d_out;                 // [4096, 1024]

    build_A_kernel<<<(NMAT * INF + 255) / 256, 256>>>(x);
    pack_W_kernel<<<(OUTF * INF + 255) / 256, 256>>>(bw, sw);

    dim3 grid(OUTF / BN, NMAT / BM);   // (8, 32)
    gemm_kernel<<<grid, 256>>>(bias, out);
}

// round 4
// speedup vs baseline: 2.1241x; 2.1241x over previous
#include <cuda_runtime.h>
#include <cuda_bf16.h>
#include <cstdint>
#include <math.h>

#define NMAT 4096
#define INF  1024
#define OUTF 1024
#define NB   8
#define K1   9216              // per-segment K
#define KTILE 32               // bf16 k per tile
#define TILES_PER_SEG (K1 / KTILE)   // 288
#define KTILES (3 * TILES_PER_SEG)   // 864
#define BM 128
#define BN 128
#define STAGES 3

// padded smem row: 32 bf16 + 8 pad = 40 elems = 80 bytes
#define ROWB 80
#define A_BYTES (BM * ROWB)    // 10240
#define B_BYTES (BN * ROWB)    // 10240
#define STAGE_BYTES (A_BYTES + B_BYTES)       // 20480
#define SMEM_TOTAL (STAGES * STAGE_BYTES)     // 61440

// ---------------- scratch (__device__ globals; no allocs allowed) ----------
__device__ __align__(128) __nv_bfloat16 g_A1[(size_t)NMAT * K1];
__device__ __align__(128) __nv_bfloat16 g_A2[(size_t)NMAT * K1];
__device__ __align__(128) __nv_bfloat16 g_W1[(size_t)OUTF * K1];
__device__ __align__(128) __nv_bfloat16 g_W2[(size_t)OUTF * K1];

// ---------------- PTX helpers (family-portable only) ------------------------
__device__ __forceinline__ uint32_t smem_u32(const void* p) {
    uint32_t a;
    asm("{ .reg .u64 t; cvta.to.shared.u64 t, %1; cvt.u32.u64 %0, t; }" : "=r"(a) : "l"(p));
    return a;
}
__device__ __forceinline__ void cp_async16(uint32_t dst, const void* src) {
    asm volatile("cp.async.cg.shared.global [%0], [%1], 16;" :: "r"(dst), "l"(src) : "memory");
}
__device__ __forceinline__ void cp_commit() {
    asm volatile("cp.async.commit_group;" ::: "memory");
}
template <int N>
__device__ __forceinline__ void cp_wait() {
    asm volatile("cp.async.wait_group %0;" :: "n"(N) : "memory");
}
__device__ __forceinline__ void ldsm_x4(uint32_t& r0, uint32_t& r1, uint32_t& r2,
                                        uint32_t& r3, uint32_t addr) {
    asm volatile("ldmatrix.sync.aligned.m8n8.x4.shared.b16 {%0,%1,%2,%3}, [%4];"
                 : "=r"(r0), "=r"(r1), "=r"(r2), "=r"(r3) : "r"(addr));
}
// NON-trans: B tile is n-major (row=n, col=k); fragment pair must vary over k.
__device__ __forceinline__ void ldsm_x2(uint32_t& r0, uint32_t& r1, uint32_t addr) {
    asm volatile("ldmatrix.sync.aligned.m8n8.x2.shared.b16 {%0,%1}, [%2];"
                 : "=r"(r0), "=r"(r1) : "r"(addr));
}
__device__ __forceinline__ void mma_bf16(float& c0, float& c1, float& c2, float& c3,
                                         uint32_t a0, uint32_t a1, uint32_t a2, uint32_t a3,
                                         uint32_t b0, uint32_t b1) {
    asm volatile("mma.sync.aligned.m16n8k16.row.col.f32.bf16.bf16.f32 "
                 "{%0,%1,%2,%3}, {%4,%5,%6,%7}, {%8,%9}, {%0,%1,%2,%3};"
                 : "+f"(c0), "+f"(c1), "+f"(c2), "+f"(c3)
                 : "r"(a0), "r"(a1), "r"(a2), "r"(a3), "r"(b0), "r"(b1));
}

// ===========================================================================
// Stage 1: A1/A2 = bf16 hi/lo of [silu(x) | bspline basis], K map k = s*1024+i
// ===========================================================================
__global__ void build_A_kernel(const float* __restrict__ x) {
    int idx = blockIdx.x * blockDim.x + threadIdx.x;
    if (idx >= NMAT * INF) return;
    int n = idx >> 10, i = idx & 1023;
    float v = x[idx];

    float vals[9];
    vals[0] = v / (1.0f + expf(-v));   // SiLU

    const float h = 0.4f, lo = -1.0f;
    float b[11];
#pragma unroll
    for (int j = 0; j < 11; j++) {
        float t0 = (float)(j - 3) * h + lo;
        float t1 = (float)(j - 2) * h + lo;
        b[j] = (v >= t0 && v < t1) ? 1.0f : 0.0f;
    }
#pragma unroll
    for (int k = 1; k <= 3; k++) {
        float inv = 1.0f / ((float)k * h + 1e-8f);
#pragma unroll
        for (int j = 0; j + k < 11; j++) {
            float tj   = (float)(j - 3) * h + lo;
            float tjk1 = (float)(j + k - 2) * h + lo;
            b[j] = (v - tj) * inv * b[j] + (tjk1 - v) * inv * b[j + 1];
        }
    }
#pragma unroll
    for (int j = 0; j < NB; j++) vals[1 + j] = b[j];

    size_t rb = (size_t)n * K1 + i;
#pragma unroll
    for (int s = 0; s < 9; s++) {
        float f = vals[s];
        __nv_bfloat16 hi = __float2bfloat16(f);
        float r = f - __bfloat162float(hi);
        g_A1[rb + s * 1024] = hi;
        g_A2[rb + s * 1024] = __float2bfloat16(r);
    }
}

// ===========================================================================
// Stage 2: W1/W2 = bf16 hi/lo of [base_weight | spline_weight], same K map
// ===========================================================================
__global__ void pack_W_kernel(const float* __restrict__ bw,
                              const float* __restrict__ sw) {
    int idx = blockIdx.x * blockDim.x + threadIdx.x;   // o*1024 + i
    if (idx >= OUTF * INF) return;
    size_t rb = (size_t)(idx >> 10) * K1 + (idx & 1023);

    float f = bw[idx];
    __nv_bfloat16 hi = __float2bfloat16(f);
    g_W1[rb] = hi;
    g_W2[rb] = __float2bfloat16(f - __bfloat162float(hi));

    const float* s = sw + (size_t)idx * NB;
#pragma unroll
    for (int j = 0; j < NB; j++) {
        float fv = s[j];
        __nv_bfloat16 h2 = __float2bfloat16(fv);
        g_W1[rb + (size_t)(j + 1) * 1024] = h2;
        g_W2[rb + (size_t)(j + 1) * 1024] = __float2bfloat16(fv - __bfloat162float(h2));
    }
}

// ===========================================================================
// Stage 3: mma.sync bf16 GEMM, 3 fused K-segments (Ah*Bh + Ah*Bl + Al*Bh)
// ===========================================================================
__device__ __forceinline__ void load_tile(uint32_t sbase, int kb, int bm, int bn, int tid) {
    int seg = kb / TILES_PER_SEG;
    int jl  = kb - seg * TILES_PER_SEG;
    const __nv_bfloat16* Asrc = (seg == 2) ? g_A2 : g_A1;
    const __nv_bfloat16* Bsrc = (seg == 1) ? g_W2 : g_W1;
    size_t kof = (size_t)jl * KTILE;

    uint32_t sA = sbase;
    uint32_t sB = sbase + A_BYTES;
#pragma unroll
    for (int r = 0; r < 2; r++) {
        int ix = tid + r * 256;          // 512 chunks of 16B
        int row = ix >> 2, c = ix & 3;
        cp_async16(sA + row * ROWB + c * 16,
                   Asrc + ((size_t)(bm + row) * K1 + kof + c * 8));
    }
#pragma unroll
    for (int r = 0; r < 2; r++) {
        int ix = tid + r * 256;
        int row = ix >> 2, c = ix & 3;
        cp_async16(sB + row * ROWB + c * 16,
                   Bsrc + ((size_t)(bn + row) * K1 + kof + c * 8));
    }
}

__global__ void __launch_bounds__(256, 2)
gemm_kernel(const float* __restrict__ bias, float* __restrict__ C) {
    extern __shared__ char smem[];
    uint32_t sb = smem_u32(smem);

    const int tid = threadIdx.x;
    const int wid = tid >> 5;
    const int lane = tid & 31;
    const int warp_m = wid & 1;        // 2 warps along M (64 each)
    const int warp_n = wid >> 1;       // 4 warps along N (32 each)
    const int bm = blockIdx.y * BM;
    const int bn = blockIdx.x * BN;

    float acc[4][4][4];                // [mt][nt][frag]
#pragma unroll
    for (int i = 0; i < 4; i++)
#pragma unroll
        for (int j = 0; j < 4; j++)
#pragma unroll
            for (int q = 0; q < 4; q++) acc[i][j][q] = 0.0f;

    // prefetch stages 0,1
    load_tile(sb + 0 * STAGE_BYTES, 0, bm, bn, tid); cp_commit();
    load_tile(sb + 1 * STAGE_BYTES, 1, bm, bn, tid); cp_commit();

    // ldmatrix per-lane address components
    const int a_row = (lane & 15);             // within 16-row A tile
    const int a_kb  = ((lane >> 4) << 3) * 2;  // byte offset of k (0 or 16B)
    const int b_row = (lane & 7);
    const int b_kb  = (((lane >> 3) & 1) << 3) * 2;

    for (int kb = 0; kb < KTILES; kb++) {
        uint32_t st = sb + (kb % STAGES) * STAGE_BYTES;
        cp_wait<1>();
        __syncthreads();
        if (kb + 2 < KTILES)
            load_tile(sb + ((kb + 2) % STAGES) * STAGE_BYTES, kb + 2, bm, bn, tid);
        cp_commit();

        uint32_t sA = st;
        uint32_t sB = st + A_BYTES;
#pragma unroll
        for (int kk = 0; kk < 2; kk++) {
            int k0b = kk * 16 * 2;   // byte offset of k-step
            uint32_t a[4][4];
#pragma unroll
            for (int mt = 0; mt < 4; mt++) {
                int m0 = warp_m * 64 + mt * 16;
                ldsm_x4(a[mt][0], a[mt][1], a[mt][2], a[mt][3],
                        sA + (m0 + a_row) * ROWB + k0b + a_kb);
            }
            uint32_t bfr[4][2];
#pragma unroll
            for (int nt = 0; nt < 4; nt++) {
                int n0 = warp_n * 32 + nt * 8;
                ldsm_x2(bfr[nt][0], bfr[nt][1],
                        sB + (n0 + b_row) * ROWB + k0b + b_kb);
            }
#pragma unroll
            for (int mt = 0; mt < 4; mt++)
#pragma unroll
                for (int nt = 0; nt < 4; nt++)
                    mma_bf16(acc[mt][nt][0], acc[mt][nt][1], acc[mt][nt][2], acc[mt][nt][3],
                             a[mt][0], a[mt][1], a[mt][2], a[mt][3],
                             bfr[nt][0], bfr[nt][1]);
        }
        __syncthreads();
    }

    // epilogue: bias + store
#pragma unroll
    for (int mt = 0; mt < 4; mt++) {
        int row0 = bm + warp_m * 64 + mt * 16 + (lane >> 2);
#pragma unroll
        for (int nt = 0; nt < 4; nt++) {
            int col = bn + warp_n * 32 + nt * 8 + (lane & 3) * 2;
            float b0 = __ldg(bias + col);
            float b1 = __ldg(bias + col + 1);
            float2 v0 = make_float2(acc[mt][nt][0] + b0, acc[mt][nt][1] + b1);
            float2 v1 = make_float2(acc[mt][nt][2] + b0, acc[mt][nt][3] + b1);
            *(float2*)(C + (size_t)row0 * OUTF + col)       = v0;
            *(float2*)(C + (size_t)(row0 + 8) * OUTF + col) = v1;
        }
    }
}

// ===========================================================================
extern "C" void kernel_launch(void* const* d_in, const int* in_sizes, int n_in,
                              void* d_out, int out_size) {
    const float* x    = (const float*)d_in[0];   // [4096,1024]
    const float* bw   = (const float*)d_in[1];   // [1024,1024]
    const float* bias = (const float*)d_in[2];   // [1024]
    const float* sw   = (const float*)d_in[3];   // [1024,1024,8]
    float* out = (float*)d_out;                  // [4096,1024]

    static bool attr_set = false;
    if (!attr_set) {
        cudaFuncSetAttribute(gemm_kernel,
                             cudaFuncAttributeMaxDynamicSharedMemorySize, SMEM_TOTAL);
        attr_set = true;
    }

    build_A_kernel<<<(NMAT * INF + 255) / 256, 256>>>(x);
    pack_W_kernel<<<(OUTF * INF + 255) / 256, 256>>>(bw, sw);

    dim3 grid(OUTF / BN, NMAT / BM);   // (8, 32) = 256 CTAs
    gemm_kernel<<<grid, 256, SMEM_TOTAL>>>(bias, out);
}

// round 5
// speedup vs baseline: 5.8691x; 2.7630x over previous
#include <cuda_runtime.h>
#include <cuda_fp16.h>
#include <cstdint>
#include <math.h>

#define NMAT 4096
#define INF  1024
#define OUTF 1024
#define NB   8
#define K1   9216              // total K (1024*9), single fp16 pass
#define KTILE 32
#define KTILES (K1 / KTILE)    // 288
#define BM 128
#define BN 128
#define STAGES 3

// padded smem row: 32 fp16 + 8 pad = 40 elems = 80 bytes
#define ROWB 80
#define A_BYTES (BM * ROWB)
#define B_BYTES (BN * ROWB)
#define STAGE_BYTES (A_BYTES + B_BYTES)       // 20480
#define SMEM_TOTAL (STAGES * STAGE_BYTES)     // 61440

// ---------------- scratch (__device__ globals; no allocs allowed) ----------
__device__ __align__(128) __half g_A[(size_t)NMAT * K1];   // [4096, 9216] fp16
__device__ __align__(128) __half g_W[(size_t)OUTF * K1];   // [1024, 9216] fp16

// ---------------- PTX helpers (family-portable only) ------------------------
__device__ __forceinline__ uint32_t smem_u32(const void* p) {
    uint32_t a;
    asm("{ .reg .u64 t; cvta.to.shared.u64 t, %1; cvt.u32.u64 %0, t; }" : "=r"(a) : "l"(p));
    return a;
}
__device__ __forceinline__ void cp_async16(uint32_t dst, const void* src) {
    asm volatile("cp.async.cg.shared.global [%0], [%1], 16;" :: "r"(dst), "l"(src) : "memory");
}
__device__ __forceinline__ void cp_commit() {
    asm volatile("cp.async.commit_group;" ::: "memory");
}
template <int N>
__device__ __forceinline__ void cp_wait() {
    asm volatile("cp.async.wait_group %0;" :: "n"(N) : "memory");
}
__device__ __forceinline__ void ldsm_x4(uint32_t& r0, uint32_t& r1, uint32_t& r2,
                                        uint32_t& r3, uint32_t addr) {
    asm volatile("ldmatrix.sync.aligned.m8n8.x4.shared.b16 {%0,%1,%2,%3}, [%4];"
                 : "=r"(r0), "=r"(r1), "=r"(r2), "=r"(r3) : "r"(addr));
}
// NON-trans: B tile is n-major (row=n, col=k); fragment pair must vary over k.
__device__ __forceinline__ void ldsm_x2(uint32_t& r0, uint32_t& r1, uint32_t addr) {
    asm volatile("ldmatrix.sync.aligned.m8n8.x2.shared.b16 {%0,%1}, [%2];"
                 : "=r"(r0), "=r"(r1) : "r"(addr));
}
__device__ __forceinline__ void mma_f16(float& c0, float& c1, float& c2, float& c3,
                                        uint32_t a0, uint32_t a1, uint32_t a2, uint32_t a3,
                                        uint32_t b0, uint32_t b1) {
    asm volatile("mma.sync.aligned.m16n8k16.row.col.f32.f16.f16.f32 "
                 "{%0,%1,%2,%3}, {%4,%5,%6,%7}, {%8,%9}, {%0,%1,%2,%3};"
                 : "+f"(c0), "+f"(c1), "+f"(c2), "+f"(c3)
                 : "r"(a0), "r"(a1), "r"(a2), "r"(a3), "r"(b0), "r"(b1));
}

// ===========================================================================
// Stage 1: A = fp16 of [silu(x) | bspline basis], K map k = slot*1024 + i
// ===========================================================================
__global__ void build_A_kernel(const float* __restrict__ x) {
    int idx = blockIdx.x * blockDim.x + threadIdx.x;
    if (idx >= NMAT * INF) return;
    int n = idx >> 10, i = idx & 1023;
    float v = x[idx];

    float vals[9];
    vals[0] = v / (1.0f + expf(-v));   // SiLU

    const float h = 0.4f, lo = -1.0f;
    float b[11];
#pragma unroll
    for (int j = 0; j < 11; j++) {
        float t0 = (float)(j - 3) * h + lo;
        float t1 = (float)(j - 2) * h + lo;
        b[j] = (v >= t0 && v < t1) ? 1.0f : 0.0f;
    }
#pragma unroll
    for (int k = 1; k <= 3; k++) {
        float inv = 1.0f / ((float)k * h + 1e-8f);
#pragma unroll
        for (int j = 0; j + k < 11; j++) {
            float tj   = (float)(j - 3) * h + lo;
            float tjk1 = (float)(j + k - 2) * h + lo;
            b[j] = (v - tj) * inv * b[j] + (tjk1 - v) * inv * b[j + 1];
        }
    }
#pragma unroll
    for (int j = 0; j < NB; j++) vals[1 + j] = b[j];

    size_t rb = (size_t)n * K1 + i;
#pragma unroll
    for (int s = 0; s < 9; s++)
        g_A[rb + s * 1024] = __float2half_rn(vals[s]);
}

// ===========================================================================
// Stage 2: W = fp16 of [base_weight | spline_weight], same K map
// ===========================================================================
__global__ void pack_W_kernel(const float* __restrict__ bw,
                              const float* __restrict__ sw) {
    int idx = blockIdx.x * blockDim.x + threadIdx.x;   // o*1024 + i
    if (idx >= OUTF * INF) return;
    size_t rb = (size_t)(idx >> 10) * K1 + (idx & 1023);

    g_W[rb] = __float2half_rn(bw[idx]);
    const float* s = sw + (size_t)idx * NB;
#pragma unroll
    for (int j = 0; j < NB; j++)
        g_W[rb + (size_t)(j + 1) * 1024] = __float2half_rn(s[j]);
}

// ===========================================================================
// Stage 3: mma.sync fp16 GEMM (single pass), C = A @ W^T + bias
// ===========================================================================
__device__ __forceinline__ void load_tile(uint32_t sbase, int kb, int bm, int bn, int tid) {
    size_t kof = (size_t)kb * KTILE;
    uint32_t sA = sbase;
    uint32_t sB = sbase + A_BYTES;
#pragma unroll
    for (int r = 0; r < 2; r++) {
        int ix = tid + r * 256;          // 512 chunks of 16B
        int row = ix >> 2, c = ix & 3;
        cp_async16(sA + row * ROWB + c * 16,
                   g_A + ((size_t)(bm + row) * K1 + kof + c * 8));
    }
#pragma unroll
    for (int r = 0; r < 2; r++) {
        int ix = tid + r * 256;
        int row = ix >> 2, c = ix & 3;
        cp_async16(sB + row * ROWB + c * 16,
                   g_W + ((size_t)(bn + row) * K1 + kof + c * 8));
    }
}

__global__ void __launch_bounds__(256, 2)
gemm_kernel(const float* __restrict__ bias, float* __restrict__ C) {
    extern __shared__ char smem[];
    uint32_t sb = smem_u32(smem);

    const int tid = threadIdx.x;
    const int wid = tid >> 5;
    const int lane = tid & 31;
    const int warp_m = wid & 1;        // 2 warps along M (64 each)
    const int warp_n = wid >> 1;       // 4 warps along N (32 each)
    const int bm = blockIdx.y * BM;
    const int bn = blockIdx.x * BN;

    float acc[4][4][4];                // [mt][nt][frag]
#pragma unroll
    for (int i = 0; i < 4; i++)
#pragma unroll
        for (int j = 0; j < 4; j++)
#pragma unroll
            for (int q = 0; q < 4; q++) acc[i][j][q] = 0.0f;

    // prefetch stages 0,1
    load_tile(sb + 0 * STAGE_BYTES, 0, bm, bn, tid); cp_commit();
    load_tile(sb + 1 * STAGE_BYTES, 1, bm, bn, tid); cp_commit();

    const int a_row = (lane & 15);
    const int a_kb  = ((lane >> 4) << 3) * 2;
    const int b_row = (lane & 7);
    const int b_kb  = (((lane >> 3) & 1) << 3) * 2;

    for (int kb = 0; kb < KTILES; kb++) {
        uint32_t st = sb + (kb % STAGES) * STAGE_BYTES;
        cp_wait<1>();
        __syncthreads();
        if (kb + 2 < KTILES)
            load_tile(sb + ((kb + 2) % STAGES) * STAGE_BYTES, kb + 2, bm, bn, tid);
        cp_commit();

        uint32_t sA = st;
        uint32_t sB = st + A_BYTES;
#pragma unroll
        for (int kk = 0; kk < 2; kk++) {
            int k0b = kk * 16 * 2;
            uint32_t a[4][4];
#pragma unroll
            for (int mt = 0; mt < 4; mt++) {
                int m0 = warp_m * 64 + mt * 16;
                ldsm_x4(a[mt][0], a[mt][1], a[mt][2], a[mt][3],
                        sA + (m0 + a_row) * ROWB + k0b + a_kb);
            }
            uint32_t bfr[4][2];
#pragma unroll
            for (int nt = 0; nt < 4; nt++) {
                int n0 = warp_n * 32 + nt * 8;
                ldsm_x2(bfr[nt][0], bfr[nt][1],
                        sB + (n0 + b_row) * ROWB + k0b + b_kb);
            }
#pragma unroll
            for (int mt = 0; mt < 4; mt++)
#pragma unroll
                for (int nt = 0; nt < 4; nt++)
                    mma_f16(acc[mt][nt][0], acc[mt][nt][1], acc[mt][nt][2], acc[mt][nt][3],
                            a[mt][0], a[mt][1], a[mt][2], a[mt][3],
                            bfr[nt][0], bfr[nt][1]);
        }
        __syncthreads();
    }

    // epilogue: bias + store
#pragma unroll
    for (int mt = 0; mt < 4; mt++) {
        int row0 = bm + warp_m * 64 + mt * 16 + (lane >> 2);
#pragma unroll
        for (int nt = 0; nt < 4; nt++) {
            int col = bn + warp_n * 32 + nt * 8 + (lane & 3) * 2;
            float b0 = __ldg(bias + col);
            float b1 = __ldg(bias + col + 1);
            float2 v0 = make_float2(acc[mt][nt][0] + b0, acc[mt][nt][1] + b1);
            float2 v1 = make_float2(acc[mt][nt][2] + b0, acc[mt][nt][3] + b1);
            *(float2*)(C + (size_t)row0 * OUTF + col)       = v0;
            *(float2*)(C + (size_t)(row0 + 8) * OUTF + col) = v1;
        }
    }
}

// ===========================================================================
extern "C" void kernel_launch(void* const* d_in, const int* in_sizes, int n_in,
                              void* d_out, int out_size) {
    const float* x    = (const float*)d_in[0];   // [4096,1024]
    const float* bw   = (const float*)d_in[1];   // [1024,1024]
    const float* bias = (const float*)d_in[2];   // [1024]
    const float* sw   = (const float*)d_in[3];   // [1024,1024,8]
    float* out = (float*)d_out;                  // [4096,1024]

    static bool attr_set = false;
    if (!attr_set) {
        cudaFuncSetAttribute(gemm_kernel,
                             cudaFuncAttributeMaxDynamicSharedMemorySize, SMEM_TOTAL);
        attr_set = true;
    }

    build_A_kernel<<<(NMAT * INF + 255) / 256, 256>>>(x);
    pack_W_kernel<<<(OUTF * INF + 255) / 256, 256>>>(bw, sw);

    dim3 grid(OUTF / BN, NMAT / BM);   // (8, 32) = 256 CTAs
    gemm_kernel<<<grid, 256, SMEM_TOTAL>>>(bias, out);
}